// round 10
// baseline (speedup 1.0000x reference)
#include <cuda_runtime.h>
#include <cstdint>
#include <math.h>

#define D_MODEL 2048
#define N_EXP   64
#define TM      128                 // tokens per CTA
#define KB      32                  // K elems per stage
#define NSTG    (D_MODEL / KB)      // 64
#define THREADS 256
#define XPITCH  36                  // floats per x row
#define WPITCH  36                  // float2 pairs per W row
#define LPITCH  68

#define XS_BYTES  18432             // 128*36*4
#define WS_BYTES  18432             // 64*36*8
#define STG_BYTES (XS_BYTES + WS_BYTES)   // 36864
#define NBUF      3
#define BIAS_OFF  (NBUF * STG_BYTES)      // 110592
#define SMEM_DYN  (BIAS_OFF + 256)        // 110848

__device__ float2 g_wint[N_EXP * D_MODEL];   // interleaved (hi, lo) tf32 pairs

__device__ __forceinline__ uint32_t smem_u32(const void* p) {
    uint32_t a;
    asm("{ .reg .u64 t; cvta.to.shared.u64 t, %1; cvt.u32.u64 %0, t; }" : "=r"(a) : "l"(p));
    return a;
}
__device__ __forceinline__ void cp16(uint32_t dst, const float* src) {
    asm volatile("cp.async.cg.shared.global [%0], [%1], 16;" :: "r"(dst), "l"(src) : "memory");
}
#define CP_COMMIT() asm volatile("cp.async.commit_group;" ::: "memory")
#define CP_WAIT(n)  asm volatile("cp.async.wait_group %0;" :: "n"(n) : "memory")

__device__ __forceinline__ uint32_t tf32_of(float f) {
    uint32_t r;
    asm("cvt.rna.tf32.f32 %0, %1;" : "=r"(r) : "f"(f));
    return r;
}
__device__ __forceinline__ void mma_dc(float& d0, float& d1, float& d2, float& d3,
                                       uint32_t a0, uint32_t a1, uint32_t a2, uint32_t a3,
                                       uint32_t b0, uint32_t b1,
                                       float c0, float c1, float c2, float c3) {
    asm volatile("mma.sync.aligned.m16n8k8.row.col.f32.tf32.tf32.f32 "
                 "{%0,%1,%2,%3},{%4,%5,%6,%7},{%8,%9},{%10,%11,%12,%13};"
                 : "=f"(d0), "=f"(d1), "=f"(d2), "=f"(d3)
                 : "r"(a0), "r"(a1), "r"(a2), "r"(a3), "r"(b0), "r"(b1),
                   "f"(c0), "f"(c1), "f"(c2), "f"(c3));
}
__device__ __forceinline__ void mma_acc(float& d0, float& d1, float& d2, float& d3,
                                        uint32_t a0, uint32_t a1, uint32_t a2, uint32_t a3,
                                        uint32_t b0, uint32_t b1) {
    asm volatile("mma.sync.aligned.m16n8k8.row.col.f32.tf32.tf32.f32 "
                 "{%0,%1,%2,%3},{%4,%5,%6,%7},{%8,%9},{%0,%1,%2,%3};"
                 : "+f"(d0), "+f"(d1), "+f"(d2), "+f"(d3)
                 : "r"(a0), "r"(a1), "r"(a2), "r"(a3), "r"(b0), "r"(b1));
}

// ---- prep: split W into interleaved tf32 (hi, lo) pairs ----
__global__ void split_w(const float* __restrict__ W) {
    const int i = blockIdx.x * 256 + threadIdx.x;
    if (i < N_EXP * D_MODEL) {
        const float v = W[i];
        const uint32_t h = tf32_of(v);
        const uint32_t l = tf32_of(v - __uint_as_float(h));
        g_wint[i] = make_float2(__uint_as_float(h), __uint_as_float(l));
    }
}

__global__ __launch_bounds__(THREADS, 2)
void router_hmma(const float* __restrict__ x,
                 const float* __restrict__ bias, float* __restrict__ out, int T)
{
    extern __shared__ float smf[];
    const uint32_t sbase = smem_u32(smf);

    const int tid  = threadIdx.x;
    const int wid  = tid >> 5;      // 0..7
    const int lane = tid & 31;
    const int g    = lane >> 2;
    const int c    = lane & 3;
    const int wr   = wid & 3;       // token row group: tokens wr*32 .. +31
    const int wc   = wid >> 2;      // expert half:     experts wc*32 .. +31
    const int t0   = blockIdx.x * TM;

    if (tid < N_EXP) smf[BIAS_OFF / 4 + tid] = bias[tid];

    auto load_stage = [&](int s, int buf) {
        const int kofs = s * KB;
        const uint32_t bb = sbase + (uint32_t)buf * STG_BYTES;
        // x: 128 rows x 32 floats; 2 threads/row, 4 x cp16 each
        {
            const int row = tid >> 1;
            const int cs  = (tid & 1) * 4;
            const uint32_t dst0 = bb + (uint32_t)row * (XPITCH * 4) + cs * 16;
            const float* src0 = x + (size_t)(t0 + row) * D_MODEL + kofs + cs * 4;
#pragma unroll
            for (int i = 0; i < 4; ++i) cp16(dst0 + i * 16, src0 + i * 4);
        }
        // W pairs: 64 rows x 32 pairs (256B); 4 threads/row, 4 x cp16 each
        {
            const int row = tid >> 2;
            const int pc  = (tid & 3) * 4;
            const uint32_t dst0 = bb + XS_BYTES
                                + (uint32_t)row * (WPITCH * 8) + pc * 16;
            const float* src0 = (const float*)(g_wint + (size_t)row * D_MODEL + kofs) + pc * 4;
#pragma unroll
            for (int i = 0; i < 4; ++i) cp16(dst0 + i * 16, src0 + i * 4);
        }
    };

    float master[2][4][4];
    float stageC[2][4][4];
#pragma unroll
    for (int mb = 0; mb < 2; ++mb)
#pragma unroll
        for (int nb = 0; nb < 4; ++nb)
#pragma unroll
            for (int q = 0; q < 4; ++q) master[mb][nb][q] = 0.0f;

    load_stage(0, 0); CP_COMMIT();
    load_stage(1, 1); CP_COMMIT();

#pragma unroll 1
    for (int s = 0; s < NSTG; ++s) {
        CP_WAIT(1);
        __syncthreads();            // buffer (s-1)%3 now free for all warps

        if (s + 2 < NSTG) load_stage(s + 2, (s + 2) % NBUF);
        CP_COMMIT();                // always commit (possibly empty group)

        const float* xb  = smf + (size_t)(s % NBUF) * (STG_BYTES / 4);
        const uint2* wbu = (const uint2*)((const char*)smf + (size_t)(s % NBUF) * STG_BYTES
                                          + XS_BYTES);

#pragma unroll
        for (int k0 = 0; k0 < KB; k0 += 8) {
            const bool fresh = ((k0 & 8) == 0);   // chunks 0, 2 start new stageC
            // A fragments (32 tokens = 2 m-blocks), split on the fly
            uint32_t ahi[2][4], alo[2][4];
#pragma unroll
            for (int mb = 0; mb < 2; ++mb) {
                const int r0 = wr * 32 + mb * 16 + g;
#pragma unroll
                for (int q = 0; q < 4; ++q) {
                    const int row = r0 + (q & 1) * 8;
                    const int col = k0 + c + ((q >> 1) * 4);
                    const float v = xb[row * XPITCH + col];
                    const uint32_t h = tf32_of(v);
                    ahi[mb][q] = h;
                    alo[mb][q] = tf32_of(v - __uint_as_float(h));
                }
            }
#pragma unroll
            for (int nb = 0; nb < 4; ++nb) {
                const int wrow = (wc * 32 + nb * 8 + g) * WPITCH + k0 + c;
                const uint2 p0 = wbu[wrow];
                const uint2 p1 = wbu[wrow + 4];
#pragma unroll
                for (int mb = 0; mb < 2; ++mb) {
                    float* sc = stageC[mb][nb];
                    if (fresh) {
                        mma_dc(sc[0], sc[1], sc[2], sc[3],
                               ahi[mb][0], ahi[mb][1], ahi[mb][2], ahi[mb][3],
                               p0.x, p1.x, 0.0f, 0.0f, 0.0f, 0.0f);
                    } else {
                        mma_acc(sc[0], sc[1], sc[2], sc[3],
                                ahi[mb][0], ahi[mb][1], ahi[mb][2], ahi[mb][3],
                                p0.x, p1.x);
                    }
                    mma_acc(sc[0], sc[1], sc[2], sc[3],
                            ahi[mb][0], ahi[mb][1], ahi[mb][2], ahi[mb][3],
                            p0.y, p1.y);
                    mma_acc(sc[0], sc[1], sc[2], sc[3],
                            alo[mb][0], alo[mb][1], alo[mb][2], alo[mb][3],
                            p0.x, p1.x);
                }
            }
            if (k0 & 8) {           // fold after chunks 1 and 3 → chains of 6
#pragma unroll
                for (int mb = 0; mb < 2; ++mb)
#pragma unroll
                    for (int nb = 0; nb < 4; ++nb)
#pragma unroll
                        for (int q = 0; q < 4; ++q)
                            master[mb][nb][q] += stageC[mb][nb][q];
            }
        }
    }

    // ---- epilogue: logits to smem (reuse stage buffers), top-2 + softmax ----
    __syncthreads();
    float* logits = smf;            // 128 x LPITCH floats = 34816 B
#pragma unroll
    for (int mb = 0; mb < 2; ++mb)
#pragma unroll
        for (int nb = 0; nb < 4; ++nb)
#pragma unroll
            for (int q = 0; q < 4; ++q) {
                const int row = wr * 32 + mb * 16 + g + ((q >> 1) * 8);
                const int col = wc * 32 + nb * 8 + 2 * c + (q & 1);
                logits[row * LPITCH + col] = master[mb][nb][q];
            }
    __syncthreads();

    if (tid < TM) {
        const float* lrow   = logits + tid * LPITCH;
        const float* bias_s = smf + BIAS_OFF / 4;
        float m1 = -INFINITY, m2 = -INFINITY;
        int   i1 = 0,         i2 = 0;
        float l[64];
#pragma unroll 8
        for (int e = 0; e < N_EXP; ++e) {
            l[e] = lrow[e] + bias_s[e];
            const float v = l[e];
            if (v > m1) { m2 = m1; i2 = i1; m1 = v; i1 = e; }
            else if (v > m2) { m2 = v; i2 = e; }
        }
        float ssum = 0.0f;
#pragma unroll 8
        for (int e = 0; e < N_EXP; ++e) ssum += __expf(l[e] - m1);
        const float inv = 1.0f / ssum;

        const int tg = t0 + tid;
        out[2 * tg + 0] = (float)i1;
        out[2 * tg + 1] = (float)i2;
        out[(size_t)2 * T + 2 * tg + 0] = inv;
        out[(size_t)2 * T + 2 * tg + 1] = __expf(m2 - m1) * inv;
    }
}

extern "C" void kernel_launch(void* const* d_in, const int* in_sizes, int n_in,
                              void* d_out, int out_size)
{
    const float* x = (const float*)d_in[0];
    const float* W = (const float*)d_in[1];
    const float* b = (const float*)d_in[2];
    float* out = (float*)d_out;

    const int T = in_sizes[0] / D_MODEL;   // 32768
    static int attr_done = 0;
    if (!attr_done) {
        cudaFuncSetAttribute(router_hmma, cudaFuncAttributeMaxDynamicSharedMemorySize, SMEM_DYN);
        attr_done = 1;
    }
    split_w<<<(N_EXP * D_MODEL + 255) / 256, 256>>>(W);
    router_hmma<<<T / TM, THREADS, SMEM_DYN>>>(x, b, out, T);
}

// round 12
// speedup vs baseline: 1.6508x; 1.6508x over previous
#include <cuda_runtime.h>
#include <cuda_fp16.h>
#include <cstdint>
#include <math.h>

#define D_MODEL 2048
#define N_EXP   64
#define TM      128                 // tokens per CTA
#define KB      32                  // K elems per stage
#define NSTG    (D_MODEL / KB)      // 64
#define THREADS 256
#define XPITCH  36                  // floats per x row (bank-perm)
#define WPITCH  20                  // uint2 per W row (bank-perm)
#define LPITCH  68

#define XS_BYTES  (TM * XPITCH * 4)        // 18432
#define WS_BYTES  (N_EXP * WPITCH * 8)     // 10240
#define STG_BYTES (XS_BYTES + WS_BYTES)    // 28672
#define BIAS_OFF  (2 * STG_BYTES)          // 57344
#define SMEM_DYN  (BIAS_OFF + 256)

#define RSCALE 64.0f
#define RINV   0.015625f

// packed W: per k-pair {f16x2(hi0,hi1), f16x2(lo0*64, lo1*64)}
__device__ uint2 g_wpk[N_EXP * (D_MODEL / 2)];

__device__ __forceinline__ uint32_t smem_u32(const void* p) {
    uint32_t a;
    asm("{ .reg .u64 t; cvta.to.shared.u64 t, %1; cvt.u32.u64 %0, t; }" : "=r"(a) : "l"(p));
    return a;
}
__device__ __forceinline__ void cp16(uint32_t dst, const void* src) {
    asm volatile("cp.async.cg.shared.global [%0], [%1], 16;" :: "r"(dst), "l"(src) : "memory");
}
#define CP_COMMIT() asm volatile("cp.async.commit_group;" ::: "memory")
#define CP_WAIT(n)  asm volatile("cp.async.wait_group %0;" :: "n"(n) : "memory")

__device__ __forceinline__ uint32_t h2u(half2 h) {
    return *reinterpret_cast<uint32_t*>(&h);
}
__device__ __forceinline__ void mma16_dc(float* d,
                                         uint32_t a0, uint32_t a1, uint32_t a2, uint32_t a3,
                                         uint32_t b0, uint32_t b1) {
    asm volatile("mma.sync.aligned.m16n8k16.row.col.f32.f16.f16.f32 "
                 "{%0,%1,%2,%3},{%4,%5,%6,%7},{%8,%9},{%10,%11,%12,%13};"
                 : "=f"(d[0]), "=f"(d[1]), "=f"(d[2]), "=f"(d[3])
                 : "r"(a0), "r"(a1), "r"(a2), "r"(a3), "r"(b0), "r"(b1),
                   "f"(0.0f), "f"(0.0f), "f"(0.0f), "f"(0.0f));
}
__device__ __forceinline__ void mma16_acc(float* d,
                                          uint32_t a0, uint32_t a1, uint32_t a2, uint32_t a3,
                                          uint32_t b0, uint32_t b1) {
    asm volatile("mma.sync.aligned.m16n8k16.row.col.f32.f16.f16.f32 "
                 "{%0,%1,%2,%3},{%4,%5,%6,%7},{%8,%9},{%0,%1,%2,%3};"
                 : "+f"(d[0]), "+f"(d[1]), "+f"(d[2]), "+f"(d[3])
                 : "r"(a0), "r"(a1), "r"(a2), "r"(a3), "r"(b0), "r"(b1));
}

// ---- prep: split W into fp16 hi + fp16 (lo*64), packed per k-pair ----
__global__ void split_w(const float* __restrict__ W) {
    const int i = blockIdx.x * 256 + threadIdx.x;          // pair index
    if (i < N_EXP * (D_MODEL / 2)) {
        const float w0 = W[2 * i], w1 = W[2 * i + 1];
        const half  h0 = __float2half_rn(w0), h1 = __float2half_rn(w1);
        const float l0 = (w0 - __half2float(h0)) * RSCALE;
        const float l1 = (w1 - __half2float(h1)) * RSCALE;
        uint2 p;
        half2 hh = __halves2half2(h0, h1);
        half2 ll = __halves2half2(__float2half_rn(l0), __float2half_rn(l1));
        p.x = h2u(hh);
        p.y = h2u(ll);
        g_wpk[i] = p;
    }
}

__global__ __launch_bounds__(THREADS, 2)
void router_hmma(const float* __restrict__ x,
                 const float* __restrict__ bias, float* __restrict__ out, int T)
{
    extern __shared__ float smf[];
    const uint32_t sbase = smem_u32(smf);

    const int tid  = threadIdx.x;
    const int wid  = tid >> 5;      // 0..7
    const int lane = tid & 31;
    const int g    = lane >> 2;
    const int c    = lane & 3;
    const int wm   = wid * 16;      // warp's 16 tokens
    const int t0   = blockIdx.x * TM;

    if (tid < N_EXP) smf[BIAS_OFF / 4 + tid] = bias[tid];

    auto load_stage = [&](int s, int buf) {
        const int kofs = s * KB;
        const uint32_t bb = sbase + (uint32_t)buf * STG_BYTES;
        // x: 128 rows x 32 floats; 2 threads/row, 4 cp16 each
        {
            const int row = tid >> 1;
            const int cs  = (tid & 1) * 4;
            const uint32_t dst0 = bb + (uint32_t)row * (XPITCH * 4) + cs * 16;
            const float* src0 = x + (size_t)(t0 + row) * D_MODEL + kofs + cs * 4;
#pragma unroll
            for (int i = 0; i < 4; ++i) cp16(dst0 + i * 16, src0 + i * 4);
        }
        // W packed: 64 rows x 16 uint2 (128B); 4 threads/row, 2 cp16 each
        {
            const int row = tid >> 2;
            const int qc  = (tid & 3) * 2;   // uint2-pair chunk (2 uint2 = 16B)
            const uint32_t dst0 = bb + XS_BYTES
                                + (uint32_t)row * (WPITCH * 8) + qc * 16;
            const uint2* src0 = g_wpk + (size_t)row * (D_MODEL / 2) + (kofs >> 1) + qc * 2;
#pragma unroll
            for (int i = 0; i < 2; ++i) cp16(dst0 + i * 16, src0 + i * 2);
        }
    };

    float master[8][4];
    float stageC[2][4];
#pragma unroll
    for (int nb = 0; nb < 8; ++nb)
#pragma unroll
        for (int q = 0; q < 4; ++q) master[nb][q] = 0.0f;

    load_stage(0, 0); CP_COMMIT();
    load_stage(1, 1); CP_COMMIT();

#pragma unroll 1
    for (int s = 0; s < NSTG; ++s) {
        if (s + 1 < NSTG) { CP_WAIT(1); } else { CP_WAIT(0); }
        __syncthreads();

        const float* xb = smf + (size_t)(s & 1) * (STG_BYTES / 4);
        const uint2* wb = (const uint2*)((const char*)smf + (size_t)(s & 1) * STG_BYTES
                                         + XS_BYTES);

        // ---- A fragments: 2 k16 chunks, fp16 split on the fly ----
        uint32_t ah[2][4], al[2][4];
#pragma unroll
        for (int ch = 0; ch < 2; ++ch) {
            const int k0 = ch * 16;
#pragma unroll
            for (int q = 0; q < 4; ++q) {
                const int row = wm + g + (q & 1) * 8;
                const int col = k0 + 2 * c + ((q >> 1) * 8);
                const float2 v = *reinterpret_cast<const float2*>(xb + row * XPITCH + col);
                const half2 h = __float22half2_rn(v);
                const float2 hf = __half22float2(h);
                float2 l;
                l.x = (v.x - hf.x) * RSCALE;
                l.y = (v.y - hf.y) * RSCALE;
                ah[ch][q] = h2u(h);
                al[ch][q] = h2u(__float22half2_rn(l));
            }
        }

#pragma unroll
        for (int nb = 0; nb < 8; ++nb) {
            const int wrow = (nb * 8 + g) * WPITCH;
            const uint2 q00 = wb[wrow + c];          // chunk0 b0: {hi, lo}
            const uint2 q01 = wb[wrow + c + 4];      // chunk0 b1
            const uint2 q10 = wb[wrow + 8 + c];      // chunk1 b0
            const uint2 q11 = wb[wrow + 8 + c + 4];  // chunk1 b1

            float* sc = stageC[nb & 1];
            // hh (exact products)
            mma16_dc (sc, ah[0][0], ah[0][1], ah[0][2], ah[0][3], q00.x, q01.x);
            mma16_acc(sc, ah[1][0], ah[1][1], ah[1][2], ah[1][3], q10.x, q11.x);
#pragma unroll
            for (int q = 0; q < 4; ++q) master[nb][q] += sc[q];
            // corrections (scale 64): hl + lh
            mma16_dc (sc, ah[0][0], ah[0][1], ah[0][2], ah[0][3], q00.y, q01.y);
            mma16_acc(sc, ah[1][0], ah[1][1], ah[1][2], ah[1][3], q10.y, q11.y);
            mma16_acc(sc, al[0][0], al[0][1], al[0][2], al[0][3], q00.x, q01.x);
            mma16_acc(sc, al[1][0], al[1][1], al[1][2], al[1][3], q10.x, q11.x);
#pragma unroll
            for (int q = 0; q < 4; ++q) master[nb][q] += sc[q] * RINV;
        }

        __syncthreads();
        if (s + 2 < NSTG) { load_stage(s + 2, s & 1); CP_COMMIT(); }
    }

    // ---- epilogue: logits to smem (reuse stage buffers), top-2 + softmax ----
    float* logits = smf;            // 128 x LPITCH floats = 34816 B < STG_BYTES*2
#pragma unroll
    for (int nb = 0; nb < 8; ++nb)
#pragma unroll
        for (int q = 0; q < 4; ++q) {
            const int row = wm + g + ((q >> 1) * 8);
            const int col = nb * 8 + 2 * c + (q & 1);
            logits[row * LPITCH + col] = master[nb][q];
        }
    __syncthreads();

    if (tid < TM) {
        const float* lrow   = logits + tid * LPITCH;
        const float* bias_s = smf + BIAS_OFF / 4;
        float m1 = -INFINITY, m2 = -INFINITY;
        int   i1 = 0,         i2 = 0;
        float l[64];
#pragma unroll 8
        for (int e = 0; e < N_EXP; ++e) {
            l[e] = lrow[e] + bias_s[e];
            const float v = l[e];
            if (v > m1) { m2 = m1; i2 = i1; m1 = v; i1 = e; }
            else if (v > m2) { m2 = v; i2 = e; }
        }
        float ssum = 0.0f;
#pragma unroll 8
        for (int e = 0; e < N_EXP; ++e) ssum += __expf(l[e] - m1);
        const float inv = 1.0f / ssum;

        const int tg = t0 + tid;
        out[2 * tg + 0] = (float)i1;
        out[2 * tg + 1] = (float)i2;
        out[(size_t)2 * T + 2 * tg + 0] = inv;
        out[(size_t)2 * T + 2 * tg + 1] = __expf(m2 - m1) * inv;
    }
}

extern "C" void kernel_launch(void* const* d_in, const int* in_sizes, int n_in,
                              void* d_out, int out_size)
{
    const float* x = (const float*)d_in[0];
    const float* W = (const float*)d_in[1];
    const float* b = (const float*)d_in[2];
    float* out = (float*)d_out;

    const int T = in_sizes[0] / D_MODEL;   // 32768
    static int attr_done = 0;
    if (!attr_done) {
        cudaFuncSetAttribute(router_hmma, cudaFuncAttributeMaxDynamicSharedMemorySize, SMEM_DYN);
        attr_done = 1;
    }
    split_w<<<(N_EXP * (D_MODEL / 2) + 255) / 256, 256>>>(W);
    router_hmma<<<T / TM, THREADS, SMEM_DYN>>>(x, b, out, T);
}

// round 13
// speedup vs baseline: 1.7050x; 1.0328x over previous
#include <cuda_runtime.h>
#include <cuda_fp16.h>
#include <cstdint>
#include <math.h>

#define D_MODEL 2048
#define N_EXP   64
#define TM      128                 // tokens per CTA
#define KB      32                  // K elems per stage
#define NSTG    (D_MODEL / KB)      // 64
#define THREADS 256
#define XPITCH  36                  // floats per x row (bank-perm)
#define WPITCH  20                  // uint2 per W row (bank-perm)
#define LPITCH  68

#define XS_BYTES  (TM * XPITCH * 4)        // 18432
#define WS_BYTES  (N_EXP * WPITCH * 8)     // 10240
#define STG_BYTES (XS_BYTES + WS_BYTES)    // 28672
#define BIAS_OFF  (2 * STG_BYTES)          // 57344
#define SMEM_DYN  (BIAS_OFF + 256)

#define RSCALE 64.0f
#define RINV   0.015625f

// packed W: per k-pair {f16x2(hi0,hi1), f16x2(lo0*64, lo1*64)}
__device__ uint2 g_wpk[N_EXP * (D_MODEL / 2)];

__device__ __forceinline__ uint32_t smem_u32(const void* p) {
    uint32_t a;
    asm("{ .reg .u64 t; cvta.to.shared.u64 t, %1; cvt.u32.u64 %0, t; }" : "=r"(a) : "l"(p));
    return a;
}
__device__ __forceinline__ void cp16(uint32_t dst, const void* src) {
    asm volatile("cp.async.cg.shared.global [%0], [%1], 16;" :: "r"(dst), "l"(src) : "memory");
}
#define CP_COMMIT() asm volatile("cp.async.commit_group;" ::: "memory")
#define CP_WAIT(n)  asm volatile("cp.async.wait_group %0;" :: "n"(n) : "memory")

__device__ __forceinline__ uint32_t h2u(half2 h) {
    return *reinterpret_cast<uint32_t*>(&h);
}
__device__ __forceinline__ void mma16_dc(float* d,
                                         uint32_t a0, uint32_t a1, uint32_t a2, uint32_t a3,
                                         uint32_t b0, uint32_t b1) {
    asm volatile("mma.sync.aligned.m16n8k16.row.col.f32.f16.f16.f32 "
                 "{%0,%1,%2,%3},{%4,%5,%6,%7},{%8,%9},{%10,%11,%12,%13};"
                 : "=f"(d[0]), "=f"(d[1]), "=f"(d[2]), "=f"(d[3])
                 : "r"(a0), "r"(a1), "r"(a2), "r"(a3), "r"(b0), "r"(b1),
                   "f"(0.0f), "f"(0.0f), "f"(0.0f), "f"(0.0f));
}
__device__ __forceinline__ void mma16_acc(float* d,
                                          uint32_t a0, uint32_t a1, uint32_t a2, uint32_t a3,
                                          uint32_t b0, uint32_t b1) {
    asm volatile("mma.sync.aligned.m16n8k16.row.col.f32.f16.f16.f32 "
                 "{%0,%1,%2,%3},{%4,%5,%6,%7},{%8,%9},{%0,%1,%2,%3};"
                 : "+f"(d[0]), "+f"(d[1]), "+f"(d[2]), "+f"(d[3])
                 : "r"(a0), "r"(a1), "r"(a2), "r"(a3), "r"(b0), "r"(b1));
}

// ---- prep: split W into fp16 hi + fp16 (lo*64), packed per k-pair ----
__global__ void split_w(const float* __restrict__ W) {
    const int i = blockIdx.x * 256 + threadIdx.x;          // pair index
    if (i < N_EXP * (D_MODEL / 2)) {
        const float w0 = W[2 * i], w1 = W[2 * i + 1];
        const half  h0 = __float2half_rn(w0), h1 = __float2half_rn(w1);
        const float l0 = (w0 - __half2float(h0)) * RSCALE;
        const float l1 = (w1 - __half2float(h1)) * RSCALE;
        uint2 p;
        half2 hh = __halves2half2(h0, h1);
        half2 ll = __halves2half2(__float2half_rn(l0), __float2half_rn(l1));
        p.x = h2u(hh);
        p.y = h2u(ll);
        g_wpk[i] = p;
    }
}

__global__ __launch_bounds__(THREADS, 2)
void router_hmma(const float* __restrict__ x,
                 const float* __restrict__ bias, float* __restrict__ out, int T)
{
    extern __shared__ float smf[];
    const uint32_t sbase = smem_u32(smf);

    const int tid  = threadIdx.x;
    const int wid  = tid >> 5;      // 0..7
    const int lane = tid & 31;
    const int g    = lane >> 2;
    const int c    = lane & 3;
    const int wm   = wid * 16;      // warp's 16 tokens
    const int t0   = blockIdx.x * TM;

    if (tid < N_EXP) smf[BIAS_OFF / 4 + tid] = bias[tid];

    auto load_stage = [&](int s, int buf) {
        const int kofs = s * KB;
        const uint32_t bb = sbase + (uint32_t)buf * STG_BYTES;
        // x: 128 rows x 32 floats; 2 threads/row, 4 cp16 each
        {
            const int row = tid >> 1;
            const int cs  = (tid & 1) * 4;
            const uint32_t dst0 = bb + (uint32_t)row * (XPITCH * 4) + cs * 16;
            const float* src0 = x + (size_t)(t0 + row) * D_MODEL + kofs + cs * 4;
#pragma unroll
            for (int i = 0; i < 4; ++i) cp16(dst0 + i * 16, src0 + i * 4);
        }
        // W packed: 64 rows x 16 uint2 (128B); 4 threads/row, 2 cp16 each
        {
            const int row = tid >> 2;
            const int qc  = (tid & 3) * 2;
            const uint32_t dst0 = bb + XS_BYTES
                                + (uint32_t)row * (WPITCH * 8) + qc * 16;
            const uint2* src0 = g_wpk + (size_t)row * (D_MODEL / 2) + (kofs >> 1) + qc * 2;
#pragma unroll
            for (int i = 0; i < 2; ++i) cp16(dst0 + i * 16, src0 + i * 2);
        }
    };

    float master[8][4];
    float stageC[8][4];             // one independent 6-chain per nb
#pragma unroll
    for (int nb = 0; nb < 8; ++nb)
#pragma unroll
        for (int q = 0; q < 4; ++q) master[nb][q] = 0.0f;

    load_stage(0, 0); CP_COMMIT();
    load_stage(1, 1); CP_COMMIT();

    const half2 sc64 = __halves2half2(__float2half_rn(RSCALE), __float2half_rn(RSCALE));

#pragma unroll 1
    for (int s = 0; s < NSTG; ++s) {
        if (s + 1 < NSTG) { CP_WAIT(1); } else { CP_WAIT(0); }
        __syncthreads();

        const float* xb = smf + (size_t)(s & 1) * (STG_BYTES / 4);
        const uint2* wb = (const uint2*)((const char*)smf + (size_t)(s & 1) * STG_BYTES
                                         + XS_BYTES);

        // ---- A fragments: 2 k16 chunks; {hi, hi*64, lo*64} fp16 sets ----
        uint32_t ah[2][4], ah64[2][4], al64[2][4];
#pragma unroll
        for (int ch = 0; ch < 2; ++ch) {
            const int k0 = ch * 16;
#pragma unroll
            for (int q = 0; q < 4; ++q) {
                const int row = wm + g + (q & 1) * 8;
                const int col = k0 + 2 * c + ((q >> 1) * 8);
                const float2 v = *reinterpret_cast<const float2*>(xb + row * XPITCH + col);
                const half2 h = __float22half2_rn(v);
                const float2 hf = __half22float2(h);
                float2 l;
                l.x = (v.x - hf.x) * RSCALE;
                l.y = (v.y - hf.y) * RSCALE;
                ah[ch][q]   = h2u(h);
                ah64[ch][q] = h2u(__hmul2(h, sc64));         // exact (x64)
                al64[ch][q] = h2u(__float22half2_rn(l));
            }
        }

        // ---- 8 independent 6-chains, all passes at scale 64 ----
#pragma unroll
        for (int nb = 0; nb < 8; ++nb) {
            const int wrow = (nb * 8 + g) * WPITCH;
            const uint2 q00 = wb[wrow + c];          // chunk0 b0: {hi, lo*64}
            const uint2 q01 = wb[wrow + c + 4];      // chunk0 b1
            const uint2 q10 = wb[wrow + 8 + c];      // chunk1 b0
            const uint2 q11 = wb[wrow + 8 + c + 4];  // chunk1 b1

            float* sc = stageC[nb];
            // hh at scale 64: (a_hi*64) * b_hi
            mma16_dc (sc, ah64[0][0], ah64[0][1], ah64[0][2], ah64[0][3], q00.x, q01.x);
            mma16_acc(sc, ah64[1][0], ah64[1][1], ah64[1][2], ah64[1][3], q10.x, q11.x);
            // hl at scale 64: a_hi * (b_lo*64)
            mma16_acc(sc, ah[0][0], ah[0][1], ah[0][2], ah[0][3], q00.y, q01.y);
            mma16_acc(sc, ah[1][0], ah[1][1], ah[1][2], ah[1][3], q10.y, q11.y);
            // lh at scale 64: (a_lo*64) * b_hi
            mma16_acc(sc, al64[0][0], al64[0][1], al64[0][2], al64[0][3], q00.x, q01.x);
            mma16_acc(sc, al64[1][0], al64[1][1], al64[1][2], al64[1][3], q10.x, q11.x);
        }
        // single fold per stage (RN), unscale by 1/64
#pragma unroll
        for (int nb = 0; nb < 8; ++nb)
#pragma unroll
            for (int q = 0; q < 4; ++q)
                master[nb][q] = fmaf(stageC[nb][q], RINV, master[nb][q]);

        __syncthreads();
        if (s + 2 < NSTG) { load_stage(s + 2, s & 1); CP_COMMIT(); }
    }

    // ---- epilogue: logits to smem (reuse stage buffers), top-2 + softmax ----
    float* logits = smf;            // 128 x LPITCH floats
#pragma unroll
    for (int nb = 0; nb < 8; ++nb)
#pragma unroll
        for (int q = 0; q < 4; ++q) {
            const int row = wm + g + ((q >> 1) * 8);
            const int col = nb * 8 + 2 * c + (q & 1);
            logits[row * LPITCH + col] = master[nb][q];
        }
    __syncthreads();

    if (tid < TM) {
        const float* lrow   = logits + tid * LPITCH;
        const float* bias_s = smf + BIAS_OFF / 4;
        float m1 = -INFINITY, m2 = -INFINITY;
        int   i1 = 0,         i2 = 0;
        float l[64];
#pragma unroll 8
        for (int e = 0; e < N_EXP; ++e) {
            l[e] = lrow[e] + bias_s[e];
            const float v = l[e];
            if (v > m1) { m2 = m1; i2 = i1; m1 = v; i1 = e; }
            else if (v > m2) { m2 = v; i2 = e; }
        }
        float ssum = 0.0f;
#pragma unroll 8
        for (int e = 0; e < N_EXP; ++e) ssum += __expf(l[e] - m1);
        const float inv = 1.0f / ssum;

        const int tg = t0 + tid;
        out[2 * tg + 0] = (float)i1;
        out[2 * tg + 1] = (float)i2;
        out[(size_t)2 * T + 2 * tg + 0] = inv;
        out[(size_t)2 * T + 2 * tg + 1] = __expf(m2 - m1) * inv;
    }
}

extern "C" void kernel_launch(void* const* d_in, const int* in_sizes, int n_in,
                              void* d_out, int out_size)
{
    const float* x = (const float*)d_in[0];
    const float* W = (const float*)d_in[1];
    const float* b = (const float*)d_in[2];
    float* out = (float*)d_out;

    const int T = in_sizes[0] / D_MODEL;   // 32768
    static int attr_done = 0;
    if (!attr_done) {
        cudaFuncSetAttribute(router_hmma, cudaFuncAttributeMaxDynamicSharedMemorySize, SMEM_DYN);
        attr_done = 1;
    }
    split_w<<<(N_EXP * (D_MODEL / 2) + 255) / 256, 256>>>(W);
    router_hmma<<<T / TM, THREADS, SMEM_DYN>>>(x, b, out, T);
}

// round 16
// speedup vs baseline: 1.7753x; 1.0412x over previous
#include <cuda_runtime.h>
#include <cuda_fp16.h>
#include <cstdint>
#include <math.h>

#define D_MODEL 2048
#define N_EXP   64
#define TM      64                  // tokens per CTA
#define KB      32                  // K elems per stage
#define NSTG    (D_MODEL / KB)      // 64
#define THREADS 256
#define XPITCH  40                  // floats per x row (conflict-free A reads)
#define WPITCH  20                  // uint2 per W row
#define LPITCH  68

#define XS_BYTES  (TM * XPITCH * 4)        // 10240
#define WS_BYTES  (N_EXP * WPITCH * 8)     // 10240
#define STG_BYTES (XS_BYTES + WS_BYTES)    // 20480
#define BIAS_OFF  (2 * STG_BYTES)          // 40960
#define SMEM_DYN  (BIAS_OFF + 256)

#define RSCALE 64.0f
#define RINV   0.015625f

// packed W: per k-pair {f16x2(hi0,hi1), f16x2(lo0*64, lo1*64)}
__device__ uint2 g_wpk[N_EXP * (D_MODEL / 2)];

__device__ __forceinline__ uint32_t smem_u32(const void* p) {
    uint32_t a;
    asm("{ .reg .u64 t; cvta.to.shared.u64 t, %1; cvt.u32.u64 %0, t; }" : "=r"(a) : "l"(p));
    return a;
}
__device__ __forceinline__ void cp16(uint32_t dst, const void* src) {
    asm volatile("cp.async.cg.shared.global [%0], [%1], 16;" :: "r"(dst), "l"(src) : "memory");
}
#define CP_COMMIT() asm volatile("cp.async.commit_group;" ::: "memory")
#define CP_WAIT(n)  asm volatile("cp.async.wait_group %0;" :: "n"(n) : "memory")

__device__ __forceinline__ uint32_t h2u(half2 h) {
    return *reinterpret_cast<uint32_t*>(&h);
}
__device__ __forceinline__ void mma16_dc(float* d,
                                         uint32_t a0, uint32_t a1, uint32_t a2, uint32_t a3,
                                         uint32_t b0, uint32_t b1) {
    asm volatile("mma.sync.aligned.m16n8k16.row.col.f32.f16.f16.f32 "
                 "{%0,%1,%2,%3},{%4,%5,%6,%7},{%8,%9},{%10,%11,%12,%13};"
                 : "=f"(d[0]), "=f"(d[1]), "=f"(d[2]), "=f"(d[3])
                 : "r"(a0), "r"(a1), "r"(a2), "r"(a3), "r"(b0), "r"(b1),
                   "f"(0.0f), "f"(0.0f), "f"(0.0f), "f"(0.0f));
}
__device__ __forceinline__ void mma16_acc(float* d,
                                          uint32_t a0, uint32_t a1, uint32_t a2, uint32_t a3,
                                          uint32_t b0, uint32_t b1) {
    asm volatile("mma.sync.aligned.m16n8k16.row.col.f32.f16.f16.f32 "
                 "{%0,%1,%2,%3},{%4,%5,%6,%7},{%8,%9},{%0,%1,%2,%3};"
                 : "+f"(d[0]), "+f"(d[1]), "+f"(d[2]), "+f"(d[3])
                 : "r"(a0), "r"(a1), "r"(a2), "r"(a3), "r"(b0), "r"(b1));
}

// ---- prep: split W into fp16 hi + fp16 (lo*64), packed per k-pair ----
__global__ void split_w(const float* __restrict__ W) {
    const int i = blockIdx.x * 256 + threadIdx.x;          // pair index
    if (i < N_EXP * (D_MODEL / 2)) {
        const float w0 = W[2 * i], w1 = W[2 * i + 1];
        const half  h0 = __float2half_rn(w0), h1 = __float2half_rn(w1);
        const float l0 = (w0 - __half2float(h0)) * RSCALE;
        const float l1 = (w1 - __half2float(h1)) * RSCALE;
        uint2 p;
        half2 hh = __halves2half2(h0, h1);
        half2 ll = __halves2half2(__float2half_rn(l0), __float2half_rn(l1));
        p.x = h2u(hh);
        p.y = h2u(ll);
        g_wpk[i] = p;
    }
}

__global__ __launch_bounds__(THREADS, 3)
void router_hmma(const float* __restrict__ x,
                 const float* __restrict__ bias, float* __restrict__ out, int T)
{
    extern __shared__ float smf[];
    const uint32_t sbase = smem_u32(smf);

    const int tid  = threadIdx.x;
    const int wid  = tid >> 5;      // 0..7
    const int lane = tid & 31;
    const int g    = lane >> 2;
    const int c    = lane & 3;
    const int wm   = (wid & 3) * 16;     // warp's 16 tokens within CTA
    const int we   = (wid >> 2) * 32;    // warp's 32 experts
    const int t0   = blockIdx.x * TM;

    if (tid < N_EXP) smf[BIAS_OFF / 4 + tid] = bias[tid];

    auto load_stage = [&](int s, int buf) {
        const int kofs = s * KB;
        const uint32_t bb = sbase + (uint32_t)buf * STG_BYTES;
        const int row = tid >> 2;        // 0..63
        const int cb  = (tid & 3) * 2;   // first 16B chunk (of 8)
        // x: 64 rows x 32 floats (128B); 4 threads/row, 2 cp16 each
        {
            const uint32_t dst0 = bb + (uint32_t)row * (XPITCH * 4) + cb * 16;
            const float* src0 = x + (size_t)(t0 + row) * D_MODEL + kofs + cb * 4;
            cp16(dst0,      src0);
            cp16(dst0 + 16, src0 + 4);
        }
        // W packed: 64 rows x 16 uint2 (128B); 4 threads/row, 2 cp16 each
        {
            const uint32_t dst0 = bb + XS_BYTES
                                + (uint32_t)row * (WPITCH * 8) + cb * 16;
            const uint2* src0 = g_wpk + (size_t)row * (D_MODEL / 2) + (kofs >> 1) + cb * 2;
            cp16(dst0,      src0);
            cp16(dst0 + 16, src0 + 2);
        }
    };

    float master[4][4];
    float stageC[4][4];             // one independent 6-chain per nb
#pragma unroll
    for (int nb = 0; nb < 4; ++nb)
#pragma unroll
        for (int q = 0; q < 4; ++q) master[nb][q] = 0.0f;

    load_stage(0, 0); CP_COMMIT();
    load_stage(1, 1); CP_COMMIT();

    const half2 sc64 = __halves2half2(__float2half_rn(RSCALE), __float2half_rn(RSCALE));

#pragma unroll 1
    for (int s = 0; s < NSTG; ++s) {
        if (s + 1 < NSTG) { CP_WAIT(1); } else { CP_WAIT(0); }
        __syncthreads();

        const float* xb = smf + (size_t)(s & 1) * (STG_BYTES / 4);
        const uint2* wb = (const uint2*)((const char*)smf + (size_t)(s & 1) * STG_BYTES
                                         + XS_BYTES);

        // ---- A fragments: 2 k16 chunks; {hi, hi*64, lo*64} fp16 sets ----
        uint32_t ah[2][4], ah64[2][4], al64[2][4];
#pragma unroll
        for (int ch = 0; ch < 2; ++ch) {
            const int k0 = ch * 16;
#pragma unroll
            for (int q = 0; q < 4; ++q) {
                const int row = wm + g + (q & 1) * 8;
                const int col = k0 + 2 * c + ((q >> 1) * 8);
                const float2 v = *reinterpret_cast<const float2*>(xb + row * XPITCH + col);
                const half2 h = __float22half2_rn(v);
                const float2 hf = __half22float2(h);
                float2 l;
                l.x = (v.x - hf.x) * RSCALE;
                l.y = (v.y - hf.y) * RSCALE;
                ah[ch][q]   = h2u(h);
                ah64[ch][q] = h2u(__hmul2(h, sc64));         // exact (x64)
                al64[ch][q] = h2u(__float22half2_rn(l));
            }
        }

        // ---- 4 independent 6-chains, all passes at scale 64 ----
#pragma unroll
        for (int nb = 0; nb < 4; ++nb) {
            const int wrow = (we + nb * 8 + g) * WPITCH;
            const uint2 q00 = wb[wrow + c];          // chunk0 b0: {hi, lo*64}
            const uint2 q01 = wb[wrow + c + 4];      // chunk0 b1
            const uint2 q10 = wb[wrow + 8 + c];      // chunk1 b0
            const uint2 q11 = wb[wrow + 8 + c + 4];  // chunk1 b1

            float* sc = stageC[nb];
            // hh at scale 64: (a_hi*64) * b_hi
            mma16_dc (sc, ah64[0][0], ah64[0][1], ah64[0][2], ah64[0][3], q00.x, q01.x);
            mma16_acc(sc, ah64[1][0], ah64[1][1], ah64[1][2], ah64[1][3], q10.x, q11.x);
            // hl at scale 64: a_hi * (b_lo*64)
            mma16_acc(sc, ah[0][0], ah[0][1], ah[0][2], ah[0][3], q00.y, q01.y);
            mma16_acc(sc, ah[1][0], ah[1][1], ah[1][2], ah[1][3], q10.y, q11.y);
            // lh at scale 64: (a_lo*64) * b_hi
            mma16_acc(sc, al64[0][0], al64[0][1], al64[0][2], al64[0][3], q00.x, q01.x);
            mma16_acc(sc, al64[1][0], al64[1][1], al64[1][2], al64[1][3], q10.x, q11.x);
        }
        // single fold per stage (RN), unscale by 1/64
#pragma unroll
        for (int nb = 0; nb < 4; ++nb)
#pragma unroll
            for (int q = 0; q < 4; ++q)
                master[nb][q] = fmaf(stageC[nb][q], RINV, master[nb][q]);

        __syncthreads();
        if (s + 2 < NSTG) { load_stage(s + 2, s & 1); CP_COMMIT(); }
    }

    // ---- epilogue: logits to smem (reuse stage buffers), top-2 + softmax ----
    float* logits = smf;            // 64 x LPITCH floats = 17408 B
#pragma unroll
    for (int nb = 0; nb < 4; ++nb)
#pragma unroll
        for (int q = 0; q < 4; ++q) {
            const int row = wm + g + ((q >> 1) * 8);
            const int col = we + nb * 8 + 2 * c + (q & 1);
            logits[row * LPITCH + col] = master[nb][q];
        }
    __syncthreads();

    if (tid < TM) {
        const float* lrow   = logits + tid * LPITCH;
        const float* bias_s = smf + BIAS_OFF / 4;
        float m1 = -INFINITY, m2 = -INFINITY;
        int   i1 = 0,         i2 = 0;
        float l[64];
#pragma unroll 8
        for (int e = 0; e < N_EXP; ++e) {
            l[e] = lrow[e] + bias_s[e];
            const float v = l[e];
            if (v > m1) { m2 = m1; i2 = i1; m1 = v; i1 = e; }
            else if (v > m2) { m2 = v; i2 = e; }
        }
        float ssum = 0.0f;
#pragma unroll 8
        for (int e = 0; e < N_EXP; ++e) ssum += __expf(l[e] - m1);
        const float inv = 1.0f / ssum;

        const int tg = t0 + tid;
        out[2 * tg + 0] = (float)i1;
        out[2 * tg + 1] = (float)i2;
        out[(size_t)2 * T + 2 * tg + 0] = inv;
        out[(size_t)2 * T + 2 * tg + 1] = __expf(m2 - m1) * inv;
    }
}

extern "C" void kernel_launch(void* const* d_in, const int* in_sizes, int n_in,
                              void* d_out, int out_size)
{
    const float* x = (const float*)d_in[0];
    const float* W = (const float*)d_in[1];
    const float* b = (const float*)d_in[2];
    float* out = (float*)d_out;

    const int T = in_sizes[0] / D_MODEL;   // 32768
    static int attr_done = 0;
    if (!attr_done) {
        cudaFuncSetAttribute(router_hmma, cudaFuncAttributeMaxDynamicSharedMemorySize, SMEM_DYN);
        attr_done = 1;
    }
    split_w<<<(N_EXP * (D_MODEL / 2) + 255) / 256, 256>>>(W);
    router_hmma<<<T / TM, THREADS, SMEM_DYN>>>(x, b, out, T);
}